// round 2
// baseline (speedup 1.0000x reference)
#include <cuda_runtime.h>
#include <math.h>

#define BB   4
#define SS   2048
#define DD   1024
#define HH   16
#define HDIM 64
#define DFFN 4096
#define MM   (BB*SS)

// ------------------------- scratch (device globals; no allocs allowed) ------
__device__ float g_q[MM * DD];              // q, then tmp for Wo gemm out
__device__ float g_k[MM * DD];              // k, then attn_out (post LN1)
__device__ float g_v[MM * DD];              // v, then Wo2 gemm out
__device__ float g_ctx[MM * DD];            // attention context
__device__ float g_ffn[(size_t)MM * DFFN];  // gelu(Wi gemm) output

// ------------------------------ helpers ------------------------------------
__device__ __forceinline__ float gelu_f(float x) {
    return 0.5f * x * (1.0f + erff(x * 0.70710678118654752f));
}

// ------------------------------ GEMM ----------------------------------------
// C[M,N] = A[M,K] @ B[K,N] + bias[N]   (optional exact GELU)
// BM=BN=128, BK=8, 256 threads, 8x8 per-thread micro-tile.
__global__ __launch_bounds__(256, 2)
void gemm_bias_kernel(const float* __restrict__ A, const float* __restrict__ B,
                      const float* __restrict__ bias, float* __restrict__ C,
                      int M, int N, int K, int act) {
    __shared__ float As[8][128];
    __shared__ float Bs[8][128];

    const int tid  = threadIdx.x;
    const int brow = blockIdx.y << 7;
    const int bcol = blockIdx.x << 7;
    const int trow = (tid >> 4) << 3;   // 0..120
    const int tcol = (tid & 15) << 3;   // 0..120

    const int ar = tid >> 1;            // 0..127
    const int ac = (tid & 1) << 2;      // 0 or 4
    const int br = tid >> 5;            // 0..7
    const int bc = (tid & 31) << 2;     // 0..124

    const float* Aptr = A + (size_t)(brow + ar) * K + ac;
    const float* Bptr = B + (size_t)br * N + bcol + bc;

    float acc[8][8];
#pragma unroll
    for (int i = 0; i < 8; i++)
#pragma unroll
        for (int j = 0; j < 8; j++) acc[i][j] = 0.0f;

    for (int k0 = 0; k0 < K; k0 += 8) {
        const float4 av = *(const float4*)(Aptr + k0);
        const float4 bv = *(const float4*)(Bptr + (size_t)k0 * N);
        __syncthreads();   // previous tile's compute done
        As[ac + 0][ar] = av.x;
        As[ac + 1][ar] = av.y;
        As[ac + 2][ar] = av.z;
        As[ac + 3][ar] = av.w;
        *(float4*)&Bs[br][bc] = bv;
        __syncthreads();
#pragma unroll
        for (int kk = 0; kk < 8; ++kk) {
            float a[8], b[8];
            const float4 a0 = *(const float4*)&As[kk][trow];
            const float4 a1 = *(const float4*)&As[kk][trow + 4];
            const float4 b0 = *(const float4*)&Bs[kk][tcol];
            const float4 b1 = *(const float4*)&Bs[kk][tcol + 4];
            a[0]=a0.x; a[1]=a0.y; a[2]=a0.z; a[3]=a0.w;
            a[4]=a1.x; a[5]=a1.y; a[6]=a1.z; a[7]=a1.w;
            b[0]=b0.x; b[1]=b0.y; b[2]=b0.z; b[3]=b0.w;
            b[4]=b1.x; b[5]=b1.y; b[6]=b1.z; b[7]=b1.w;
#pragma unroll
            for (int i = 0; i < 8; i++)
#pragma unroll
                for (int j = 0; j < 8; j++) acc[i][j] += a[i] * b[j];
        }
    }

    const float4 bb0 = *(const float4*)&bias[bcol + tcol];
    const float4 bb1 = *(const float4*)&bias[bcol + tcol + 4];
    const float bvals[8] = {bb0.x, bb0.y, bb0.z, bb0.w, bb1.x, bb1.y, bb1.z, bb1.w};

#pragma unroll
    for (int i = 0; i < 8; i++) {
        const size_t row = (size_t)(brow + trow + i);
        float r[8];
#pragma unroll
        for (int j = 0; j < 8; j++) {
            float x = acc[i][j] + bvals[j];
            r[j] = act ? gelu_f(x) : x;
        }
        *(float4*)&C[row * N + bcol + tcol]     = make_float4(r[0], r[1], r[2], r[3]);
        *(float4*)&C[row * N + bcol + tcol + 4] = make_float4(r[4], r[5], r[6], r[7]);
    }
}

// ------------------------------ attention -----------------------------------
// Flash-style: one CTA handles 64 query rows of one (b,h); sweeps K in 64-row
// tiles with online softmax. 256 threads, each owns a 4x4 score/output tile.
// K tile stored with XOR-4 column swizzle for conflict-free LDS.128.
__global__ __launch_bounds__(256, 2)
void attn_kernel(const float* __restrict__ Q, const float* __restrict__ Kg,
                 const float* __restrict__ Vg, const float* __restrict__ mask,
                 float* __restrict__ O) {
    __shared__ float Qs[64][64];
    __shared__ float KP[64][64];   // K tile (swizzled), then reused for P
    __shared__ float Vs[64][64];

    const int tid = threadIdx.x;
    const int bh  = blockIdx.y;
    const int b   = bh >> 4;
    const int h   = bh & 15;
    const int q0  = blockIdx.x << 6;
    const int tx  = tid & 15;
    const int ty  = tid >> 4;

    // load Q tile, pre-scaled by 1/sqrt(64)
    for (int i = tid; i < 64 * 16; i += 256) {
        const int r = i >> 4;
        const int c = (i & 15) << 2;
        float4 qv = *(const float4*)&Q[(size_t)(b * SS + q0 + r) * DD + h * HDIM + c];
        qv.x *= 0.125f; qv.y *= 0.125f; qv.z *= 0.125f; qv.w *= 0.125f;
        *(float4*)&Qs[r][c] = qv;
    }

    float m_[4], l_[4], o_[4][4];
#pragma unroll
    for (int i = 0; i < 4; i++) {
        m_[i] = -3.0e38f;
        l_[i] = 0.0f;
#pragma unroll
        for (int j = 0; j < 4; j++) o_[i][j] = 0.0f;
    }

    for (int k0 = 0; k0 < SS; k0 += 64) {
        __syncthreads();   // protect KP/Vs reuse (also covers Qs visibility)
        for (int i = tid; i < 64 * 16; i += 256) {
            const int r = i >> 4;
            const int c = (i & 15) << 2;
            const size_t gidx = (size_t)(b * SS + k0 + r) * DD + h * HDIM + c;
            const float4 kv = *(const float4*)&Kg[gidx];
            const int sc = c ^ (((r >> 2) & 7) << 2);
            *(float4*)&KP[r][sc] = kv;
            *(float4*)&Vs[r][c]  = *(const float4*)&Vg[gidx];
        }
        __syncthreads();

        // scores: S = Q @ K^T (4x4 per thread)
        float s[4][4];
#pragma unroll
        for (int i = 0; i < 4; i++)
#pragma unroll
            for (int j = 0; j < 4; j++) s[i][j] = 0.0f;

        const int swz = (tx & 7) << 2;
#pragma unroll
        for (int kk = 0; kk < 64; kk += 4) {
            float4 qv[4], kv[4];
#pragma unroll
            for (int i = 0; i < 4; i++) qv[i] = *(const float4*)&Qs[4 * ty + i][kk];
            const int col = kk ^ swz;
#pragma unroll
            for (int j = 0; j < 4; j++) kv[j] = *(const float4*)&KP[4 * tx + j][col];
#pragma unroll
            for (int i = 0; i < 4; i++)
#pragma unroll
                for (int j = 0; j < 4; j++)
                    s[i][j] += qv[i].x * kv[j].x + qv[i].y * kv[j].y
                             + qv[i].z * kv[j].z + qv[i].w * kv[j].w;
        }

        // additive mask (broadcast over queries)
        const float4 mk = *(const float4*)&mask[b * SS + k0 + 4 * tx];
#pragma unroll
        for (int i = 0; i < 4; i++) {
            s[i][0] += mk.x; s[i][1] += mk.y; s[i][2] += mk.z; s[i][3] += mk.w;
        }

        // online softmax update (row groups of 16 lanes)
#pragma unroll
        for (int i = 0; i < 4; i++) {
            float rm = fmaxf(fmaxf(s[i][0], s[i][1]), fmaxf(s[i][2], s[i][3]));
#pragma unroll
            for (int off = 1; off < 16; off <<= 1)
                rm = fmaxf(rm, __shfl_xor_sync(0xffffffffu, rm, off));
            const float mn   = fmaxf(m_[i], rm);
            const float corr = __expf(m_[i] - mn);
            float rs = 0.0f;
#pragma unroll
            for (int j = 0; j < 4; j++) {
                s[i][j] = __expf(s[i][j] - mn);
                rs += s[i][j];
            }
#pragma unroll
            for (int off = 1; off < 16; off <<= 1)
                rs += __shfl_xor_sync(0xffffffffu, rs, off);
            l_[i] = l_[i] * corr + rs;
            m_[i] = mn;
#pragma unroll
            for (int j = 0; j < 4; j++) o_[i][j] *= corr;
        }

        __syncthreads();   // everyone done reading KP as K
#pragma unroll
        for (int i = 0; i < 4; i++)
#pragma unroll
            for (int j = 0; j < 4; j++) KP[4 * ty + i][4 * tx + j] = s[i][j];
        __syncthreads();

        // O += P @ V
#pragma unroll
        for (int kk = 0; kk < 64; kk += 4) {
            float4 pv[4], vv[4];
#pragma unroll
            for (int i = 0; i < 4; i++) pv[i] = *(const float4*)&KP[4 * ty + i][kk];
#pragma unroll
            for (int t = 0; t < 4; t++) vv[t] = *(const float4*)&Vs[kk + t][4 * tx];
#pragma unroll
            for (int i = 0; i < 4; i++) {
                o_[i][0] += pv[i].x * vv[0].x + pv[i].y * vv[1].x + pv[i].z * vv[2].x + pv[i].w * vv[3].x;
                o_[i][1] += pv[i].x * vv[0].y + pv[i].y * vv[1].y + pv[i].z * vv[2].y + pv[i].w * vv[3].y;
                o_[i][2] += pv[i].x * vv[0].z + pv[i].y * vv[1].z + pv[i].z * vv[2].z + pv[i].w * vv[3].z;
                o_[i][3] += pv[i].x * vv[0].w + pv[i].y * vv[1].w + pv[i].z * vv[2].w + pv[i].w * vv[3].w;
            }
        }
    }

#pragma unroll
    for (int i = 0; i < 4; i++) {
        const float inv = 1.0f / l_[i];
        const float4 res = make_float4(o_[i][0] * inv, o_[i][1] * inv,
                                       o_[i][2] * inv, o_[i][3] * inv);
        *(float4*)&O[(size_t)(b * SS + q0 + 4 * ty + i) * DD + h * HDIM + 4 * tx] = res;
    }
}

// ------------------------------ LayerNorm -----------------------------------
__device__ __forceinline__ float block_sum_256(float v) {
    __shared__ float red[8];
    const int lane = threadIdx.x & 31;
    const int w    = threadIdx.x >> 5;
#pragma unroll
    for (int off = 16; off; off >>= 1) v += __shfl_xor_sync(0xffffffffu, v, off);
    __syncthreads();                 // protect red across calls
    if (lane == 0) red[w] = v;
    __syncthreads();
    return red[0] + red[1] + red[2] + red[3] + red[4] + red[5] + red[6] + red[7];
}

// out = LayerNorm(Y + R) * g + b, per 1024-wide row, 256 threads (f4 each)
__global__ __launch_bounds__(256)
void ln_kernel(const float* __restrict__ Y, const float* __restrict__ R,
               const float* __restrict__ g, const float* __restrict__ bta,
               float* __restrict__ out) {
    const int row = blockIdx.x;
    const int tid = threadIdx.x;
    float4 v = ((const float4*)(Y + (size_t)row * DD))[tid];
    const float4 r = ((const float4*)(R + (size_t)row * DD))[tid];
    v.x += r.x; v.y += r.y; v.z += r.z; v.w += r.w;

    const float tot  = block_sum_256(v.x + v.y + v.z + v.w);
    const float mean = tot * (1.0f / 1024.0f);
    const float dx = v.x - mean, dy = v.y - mean, dz = v.z - mean, dw = v.w - mean;
    const float tot2 = block_sum_256(dx * dx + dy * dy + dz * dz + dw * dw);
    const float rstd = rsqrtf(tot2 * (1.0f / 1024.0f) + 1e-12f);

    const float4 gg = ((const float4*)g)[tid];
    const float4 bb = ((const float4*)bta)[tid];
    float4 o;
    o.x = dx * rstd * gg.x + bb.x;
    o.y = dy * rstd * gg.y + bb.y;
    o.z = dz * rstd * gg.z + bb.z;
    o.w = dw * rstd * gg.w + bb.w;
    ((float4*)(out + (size_t)row * DD))[tid] = o;
}

// ------------------------------ launch --------------------------------------
extern "C" void kernel_launch(void* const* d_in, const int* in_sizes, int n_in,
                              void* d_out, int out_size) {
    const float* x    = (const float*)d_in[0];
    const float* mask = (const float*)d_in[1];
    const float* Wq   = (const float*)d_in[2];
    const float* bq   = (const float*)d_in[3];
    const float* Wk   = (const float*)d_in[4];
    const float* bk   = (const float*)d_in[5];
    const float* Wv   = (const float*)d_in[6];
    const float* bv   = (const float*)d_in[7];
    const float* Wo   = (const float*)d_in[8];
    const float* bo   = (const float*)d_in[9];
    const float* ln1g = (const float*)d_in[10];
    const float* ln1b = (const float*)d_in[11];
    const float* Wi   = (const float*)d_in[12];
    const float* bi   = (const float*)d_in[13];
    const float* Wo2  = (const float*)d_in[14];
    const float* bo2  = (const float*)d_in[15];
    const float* ln2g = (const float*)d_in[16];
    const float* ln2b = (const float*)d_in[17];
    float* out = (float*)d_out;

    float *q, *k, *v, *ctx, *ffn;
    cudaGetSymbolAddress((void**)&q,   g_q);
    cudaGetSymbolAddress((void**)&k,   g_k);
    cudaGetSymbolAddress((void**)&v,   g_v);
    cudaGetSymbolAddress((void**)&ctx, g_ctx);
    cudaGetSymbolAddress((void**)&ffn, g_ffn);

    const dim3 blk(256);
    const dim3 gD(DD / 128, MM / 128);     // N=1024 gemms
    const dim3 gF(DFFN / 128, MM / 128);   // N=4096 gemm
    const dim3 gAtt(SS / 64, BB * HH);

    // QKV projections
    gemm_bias_kernel<<<gD, blk>>>(x, Wq, bq, q, MM, DD, DD, 0);
    gemm_bias_kernel<<<gD, blk>>>(x, Wk, bk, k, MM, DD, DD, 0);
    gemm_bias_kernel<<<gD, blk>>>(x, Wv, bv, v, MM, DD, DD, 0);

    // attention -> ctx
    attn_kernel<<<gAtt, blk>>>(q, k, v, mask, ctx);

    // ctx @ Wo + bo -> q (tmp); LN1(q + x) -> k (attn_out)
    gemm_bias_kernel<<<gD, blk>>>(ctx, Wo, bo, q, MM, DD, DD, 0);
    ln_kernel<<<MM, blk>>>(q, x, ln1g, ln1b, k);

    // FFN: gelu(attn_out @ Wi + bi) -> ffn ; ffn @ Wo2 + bo2 -> v (tmp)
    gemm_bias_kernel<<<gF, blk>>>(k, Wi, bi, ffn, MM, DFFN, DD, 1);
    gemm_bias_kernel<<<gD, blk>>>(ffn, Wo2, bo2, v, MM, DD, DFFN, 0);

    // LN2(v + attn_out) -> out
    ln_kernel<<<MM, blk>>>(v, k, ln2g, ln2b, out);
}

// round 4
// speedup vs baseline: 2.0179x; 2.0179x over previous
#include <cuda_runtime.h>
#include <cuda_bf16.h>
#include <math.h>
#include <stdint.h>

#define BB 4
#define SS 2048
#define DD 1024
#define DFFN 4096
#define MM (BB*SS)
#define QKVW 3072

__device__ float g_qkv[(size_t)MM * QKVW];
__device__ float g_ctx[(size_t)MM * DD];
__device__ float g_tmp[(size_t)MM * DD];
__device__ float g_attn[(size_t)MM * DD];
__device__ __nv_bfloat16 g_ah[(size_t)MM * DD], g_al[(size_t)MM * DD];
__device__ __nv_bfloat16 g_fh[(size_t)MM * DFFN], g_fl[(size_t)MM * DFFN];
#define W_QKV 0u
#define W_O   (3u*1024*1024)
#define W_I   (4u*1024*1024)
#define W_O2  (8u*1024*1024)
__device__ __nv_bfloat16 g_wh[12u*1024*1024], g_wl[12u*1024*1024];
__device__ float g_b3[QKVW];

__device__ __forceinline__ float gelu_f(float x) {
    return 0.5f * x * (1.0f + erff(x * 0.70710678118654752f));
}
__device__ __forceinline__ uint32_t s2u(const void* p) {
    uint32_t a;
    asm("{ .reg .u64 t; cvta.to.shared.u64 t, %1; cvt.u32.u64 %0, t; }" : "=r"(a) : "l"(p));
    return a;
}
// swizzle within a 128-row x 64-col bf16 tile (128B rows): XOR 16B-unit by row%8
__device__ __forceinline__ uint32_t swz(uint32_t off) {
    return off ^ (((off >> 7) & 7u) << 4);
}
__device__ __forceinline__ void cpa(uint32_t dst, const void* src) {
    asm volatile("cp.async.cg.shared.global [%0], [%1], 16;" :: "r"(dst), "l"(src));
}
__device__ __forceinline__ void ldsm4(uint32_t* r, uint32_t addr) {
    asm volatile("ldmatrix.sync.aligned.m8n8.x4.shared.b16 {%0,%1,%2,%3}, [%4];"
        : "=r"(r[0]), "=r"(r[1]), "=r"(r[2]), "=r"(r[3]) : "r"(addr));
}
__device__ __forceinline__ void mma16816(float* d, const uint32_t* a, const uint32_t* b) {
    asm volatile("mma.sync.aligned.m16n8k16.row.col.f32.bf16.bf16.f32 "
        "{%0,%1,%2,%3}, {%4,%5,%6,%7}, {%8,%9}, {%0,%1,%2,%3};"
        : "+f"(d[0]), "+f"(d[1]), "+f"(d[2]), "+f"(d[3])
        : "r"(a[0]), "r"(a[1]), "r"(a[2]), "r"(a[3]), "r"(b[0]), "r"(b[1]));
}

// W [K,N] fp32 -> hi/lo [N,K] bf16
__global__ __launch_bounds__(256)
void wsplit_kernel(const float* __restrict__ W, int N, int K,
                   __nv_bfloat16* __restrict__ hi, __nv_bfloat16* __restrict__ lo) {
    __shared__ float t[32][33];
    const int tx = threadIdx.x, ty = threadIdx.y;
    const int n0 = blockIdx.x * 32, k0 = blockIdx.y * 32;
    for (int j = ty; j < 32; j += 8) t[j][tx] = W[(size_t)(k0 + j) * N + n0 + tx];
    __syncthreads();
    for (int j = ty; j < 32; j += 8) {
        const float w = t[tx][j];
        const size_t o = (size_t)(n0 + j) * K + k0 + tx;
        const __nv_bfloat16 h = __float2bfloat16_rn(w);
        hi[o] = h;
        lo[o] = __float2bfloat16_rn(w - __bfloat162float(h));
    }
}

__global__ __launch_bounds__(256)
void split_kernel(const float* __restrict__ in, __nv_bfloat16* __restrict__ hi,
                  __nv_bfloat16* __restrict__ lo, int n4) {
    for (int i = blockIdx.x * 256 + threadIdx.x; i < n4; i += gridDim.x * 256) {
        const float4 v = ((const float4*)in)[i];
        const __nv_bfloat16 h0 = __float2bfloat16_rn(v.x), h1 = __float2bfloat16_rn(v.y);
        const __nv_bfloat16 h2 = __float2bfloat16_rn(v.z), h3 = __float2bfloat16_rn(v.w);
        ((__nv_bfloat162*)hi)[2*i+0] = __halves2bfloat162(h0, h1);
        ((__nv_bfloat162*)hi)[2*i+1] = __halves2bfloat162(h2, h3);
        ((__nv_bfloat162*)lo)[2*i+0] = __halves2bfloat162(
            __float2bfloat16_rn(v.x - __bfloat162float(h0)),
            __float2bfloat16_rn(v.y - __bfloat162float(h1)));
        ((__nv_bfloat162*)lo)[2*i+1] = __halves2bfloat162(
            __float2bfloat16_rn(v.z - __bfloat162float(h2)),
            __float2bfloat16_rn(v.w - __bfloat162float(h3)));
    }
}

__global__ void pack3_kernel(const float* a, const float* b, const float* c, float* o) {
    const float* s = (blockIdx.x == 0) ? a : (blockIdx.x == 1) ? b : c;
    o[blockIdx.x * 1024 + threadIdx.x] = s[threadIdx.x];
}

// ---- mma.sync bf16 GEMM: C[M,N] = (Ah+Al)[M,K] @ (Bh+Bl)[N,K]^T + bias ----
// CTA 128x128, BK=64, 3-stage cp.async pipeline. 3-term split.
#define STG_B 65536
#define T_AH 0
#define T_AL 16384
#define T_BH 32768
#define T_BL 49152
#define GSMEM (3*STG_B)

__device__ __forceinline__ void load_stage(uint32_t sbase,
    const __nv_bfloat16* __restrict__ Ah, const __nv_bfloat16* __restrict__ Al,
    const __nv_bfloat16* __restrict__ Bh, const __nv_bfloat16* __restrict__ Bl,
    int K, int m0, int n0, int kb) {
    for (int i = threadIdx.x; i < 1024; i += 256) {
        const int row = i >> 3, cc = (i & 7) << 3;
        const uint32_t so = swz((uint32_t)(row * 128 + cc * 2));
        const size_t ka = (size_t)(m0 + row) * K + kb + cc;
        const size_t kbx = (size_t)(n0 + row) * K + kb + cc;
        cpa(sbase + T_AH + so, Ah + ka);
        cpa(sbase + T_AL + so, Al + ka);
        cpa(sbase + T_BH + so, Bh + kbx);
        cpa(sbase + T_BL + so, Bl + kbx);
    }
}

__global__ __launch_bounds__(256, 1)
void gemm_tc(const __nv_bfloat16* __restrict__ Ah, const __nv_bfloat16* __restrict__ Al,
             const __nv_bfloat16* __restrict__ Bh, const __nv_bfloat16* __restrict__ Bl,
             const float* __restrict__ bias, float* __restrict__ Cf,
             __nv_bfloat16* __restrict__ Ch, __nv_bfloat16* __restrict__ Cl,
             int N, int K, int act) {
    extern __shared__ char smv[];
    const uint32_t sb = s2u(smv);
    const int tid = threadIdx.x, lane = tid & 31, wid = tid >> 5;
    const int wm = wid & 3, wn = wid >> 2;           // 4x2 warp grid
    const int m0 = blockIdx.y << 7, n0 = blockIdx.x << 7;
    const int nc = K >> 6;

    float acc[2][8][4];
#pragma unroll
    for (int i = 0; i < 2; i++)
#pragma unroll
        for (int j = 0; j < 8; j++)
#pragma unroll
            for (int q = 0; q < 4; q++) acc[i][j][q] = 0.0f;

    // prologue: stages 0,1
    load_stage(sb, Ah, Al, Bh, Bl, K, m0, n0, 0);
    asm volatile("cp.async.commit_group;" ::: "memory");
    load_stage(sb + STG_B, Ah, Al, Bh, Bl, K, m0, n0, 64);
    asm volatile("cp.async.commit_group;" ::: "memory");

    // per-thread ldmatrix source coords (within tile)
    const int a_r = (lane & 15);
    const int a_c = (lane >> 4) << 3;
    const int b_r = (lane & 7) + ((lane >> 4) << 3);
    const int b_c = ((lane >> 3) & 1) << 3;

    for (int c = 0; c < nc; c++) {
        if (c + 2 < nc)
            load_stage(sb + (uint32_t)((c + 2) % 3) * STG_B, Ah, Al, Bh, Bl,
                       K, m0, n0, (c + 2) << 6);
        asm volatile("cp.async.commit_group;" ::: "memory");
        asm volatile("cp.async.wait_group 2;" ::: "memory");
        __syncthreads();

        const uint32_t st = sb + (uint32_t)(c % 3) * STG_B;
#pragma unroll
        for (int ks = 0; ks < 4; ks++) {
            uint32_t afh[2][4], afl[2][4], bfh[8][2], bfl[8][2];
#pragma unroll
            for (int mt = 0; mt < 2; mt++) {
                const uint32_t off = swz((uint32_t)((wm*32 + mt*16 + a_r)*128 + (ks*16 + a_c)*2));
                ldsm4(afh[mt], st + T_AH + off);
                ldsm4(afl[mt], st + T_AL + off);
            }
#pragma unroll
            for (int p = 0; p < 4; p++) {
                const uint32_t off = swz((uint32_t)((wn*64 + p*16 + b_r)*128 + (ks*16 + b_c)*2));
                uint32_t t4[4];
                ldsm4(t4, st + T_BH + off);
                bfh[2*p][0]=t4[0]; bfh[2*p][1]=t4[1]; bfh[2*p+1][0]=t4[2]; bfh[2*p+1][1]=t4[3];
                ldsm4(t4, st + T_BL + off);
                bfl[2*p][0]=t4[0]; bfl[2*p][1]=t4[1]; bfl[2*p+1][0]=t4[2]; bfl[2*p+1][1]=t4[3];
            }
#pragma unroll
            for (int mt = 0; mt < 2; mt++)
#pragma unroll
                for (int nt = 0; nt < 8; nt++) {
                    mma16816(acc[mt][nt], afh[mt], bfh[nt]);
                    mma16816(acc[mt][nt], afh[mt], bfl[nt]);
                    mma16816(acc[mt][nt], afl[mt], bfh[nt]);
                }
        }
        __syncthreads();
    }

    // epilogue: c-frag thread t: rows t/4 and t/4+8, cols 2*(t%4)..+1 of each 16x8 tile
    const int rbase = m0 + wm * 32 + (lane >> 2);
    const int cbase = n0 + wn * 64 + ((lane & 3) << 1);
#pragma unroll
    for (int mt = 0; mt < 2; mt++) {
#pragma unroll
        for (int nt = 0; nt < 8; nt++) {
            const int col = cbase + nt * 8;
            const float2 bv = *(const float2*)&bias[col];
            float v0 = acc[mt][nt][0] + bv.x, v1 = acc[mt][nt][1] + bv.y;
            float v2 = acc[mt][nt][2] + bv.x, v3 = acc[mt][nt][3] + bv.y;
            if (act) { v0 = gelu_f(v0); v1 = gelu_f(v1); v2 = gelu_f(v2); v3 = gelu_f(v3); }
            const size_t r0 = (size_t)(rbase + mt * 16);
            const size_t r1 = r0 + 8;
            if (Cf) {
                *(float2*)&Cf[r0 * N + col] = make_float2(v0, v1);
                *(float2*)&Cf[r1 * N + col] = make_float2(v2, v3);
            } else {
                const __nv_bfloat16 h0 = __float2bfloat16_rn(v0), h1 = __float2bfloat16_rn(v1);
                const __nv_bfloat16 h2 = __float2bfloat16_rn(v2), h3 = __float2bfloat16_rn(v3);
                *(__nv_bfloat162*)&Ch[r0 * N + col] = __halves2bfloat162(h0, h1);
                *(__nv_bfloat162*)&Ch[r1 * N + col] = __halves2bfloat162(h2, h3);
                *(__nv_bfloat162*)&Cl[r0 * N + col] = __halves2bfloat162(
                    __float2bfloat16_rn(v0 - __bfloat162float(h0)),
                    __float2bfloat16_rn(v1 - __bfloat162float(h1)));
                *(__nv_bfloat162*)&Cl[r1 * N + col] = __halves2bfloat162(
                    __float2bfloat16_rn(v2 - __bfloat162float(h2)),
                    __float2bfloat16_rn(v3 - __bfloat162float(h3)));
            }
        }
    }
}

// ---- attention (fp32 flash, packed qkv input) ----
__global__ __launch_bounds__(256, 2)
void attn_kernel(const float* __restrict__ QKV, const float* __restrict__ mask,
                 float* __restrict__ O) {
    __shared__ float Qs[64][64];
    __shared__ float KP[64][64];
    __shared__ float Vs[64][64];
    const int tid = threadIdx.x;
    const int b = blockIdx.y >> 4, h = blockIdx.y & 15;
    const int q0 = blockIdx.x << 6;
    const int tx = tid & 15, ty = tid >> 4;

    for (int i = tid; i < 64 * 16; i += 256) {
        const int r = i >> 4, c = (i & 15) << 2;
        float4 qv = *(const float4*)&QKV[(size_t)(b*SS + q0 + r) * QKVW + h*64 + c];
        qv.x *= 0.125f; qv.y *= 0.125f; qv.z *= 0.125f; qv.w *= 0.125f;
        *(float4*)&Qs[r][c] = qv;
    }
    float m_[4], l_[4], o_[4][4];
#pragma unroll
    for (int i = 0; i < 4; i++) {
        m_[i] = -3.0e38f; l_[i] = 0.0f;
#pragma unroll
        for (int j = 0; j < 4; j++) o_[i][j] = 0.0f;
    }
    for (int k0 = 0; k0 < SS; k0 += 64) {
        __syncthreads();
        for (int i = tid; i < 64 * 16; i += 256) {
            const int r = i >> 4, c = (i & 15) << 2;
            const size_t g = (size_t)(b*SS + k0 + r) * QKVW + h*64 + c;
            const float4 kv = *(const float4*)&QKV[g + DD];
            *(float4*)&KP[r][c ^ (((r >> 2) & 7) << 2)] = kv;
            *(float4*)&Vs[r][c] = *(const float4*)&QKV[g + 2*DD];
        }
        __syncthreads();
        float s[4][4];
#pragma unroll
        for (int i = 0; i < 4; i++)
#pragma unroll
            for (int j = 0; j < 4; j++) s[i][j] = 0.0f;
        const int swzc = (tx & 7) << 2;
#pragma unroll
        for (int kk = 0; kk < 64; kk += 4) {
            float4 qv[4], kv[4];
#pragma unroll
            for (int i = 0; i < 4; i++) qv[i] = *(const float4*)&Qs[4*ty + i][kk];
            const int col = kk ^ swzc;
#pragma unroll
            for (int j = 0; j < 4; j++) kv[j] = *(const float4*)&KP[4*tx + j][col];
#pragma unroll
            for (int i = 0; i < 4; i++)
#pragma unroll
                for (int j = 0; j < 4; j++)
                    s[i][j] += qv[i].x*kv[j].x + qv[i].y*kv[j].y + qv[i].z*kv[j].z + qv[i].w*kv[j].w;
        }
        const float4 mk = *(const float4*)&mask[b*SS + k0 + 4*tx];
#pragma unroll
        for (int i = 0; i < 4; i++) {
            s[i][0] += mk.x; s[i][1] += mk.y; s[i][2] += mk.z; s[i][3] += mk.w;
        }
#pragma unroll
        for (int i = 0; i < 4; i++) {
            float rm = fmaxf(fmaxf(s[i][0], s[i][1]), fmaxf(s[i][2], s[i][3]));
#pragma unroll
            for (int off = 1; off < 16; off <<= 1)
                rm = fmaxf(rm, __shfl_xor_sync(0xffffffffu, rm, off));
            const float mn = fmaxf(m_[i], rm);
            const float corr = __expf(m_[i] - mn);
            float rs = 0.0f;
#pragma unroll
            for (int j = 0; j < 4; j++) { s[i][j] = __expf(s[i][j] - mn); rs += s[i][j]; }
#pragma unroll
            for (int off = 1; off < 16; off <<= 1)
                rs += __shfl_xor_sync(0xffffffffu, rs, off);
            l_[i] = l_[i] * corr + rs; m_[i] = mn;
#pragma unroll
            for (int j = 0; j < 4; j++) o_[i][j] *= corr;
        }
        __syncthreads();
#pragma unroll
        for (int i = 0; i < 4; i++)
#pragma unroll
            for (int j = 0; j < 4; j++) KP[4*ty + i][4*tx + j] = s[i][j];
        __syncthreads();
#pragma unroll
        for (int kk = 0; kk < 64; kk += 4) {
            float4 pv[4], vv[4];
#pragma unroll
            for (int i = 0; i < 4; i++) pv[i] = *(const float4*)&KP[4*ty + i][kk];
#pragma unroll
            for (int t = 0; t < 4; t++) vv[t] = *(const float4*)&Vs[kk + t][4*tx];
#pragma unroll
            for (int i = 0; i < 4; i++) {
                o_[i][0] += pv[i].x*vv[0].x + pv[i].y*vv[1].x + pv[i].z*vv[2].x + pv[i].w*vv[3].x;
                o_[i][1] += pv[i].x*vv[0].y + pv[i].y*vv[1].y + pv[i].z*vv[2].y + pv[i].w*vv[3].y;
                o_[i][2] += pv[i].x*vv[0].z + pv[i].y*vv[1].z + pv[i].z*vv[2].z + pv[i].w*vv[3].z;
                o_[i][3] += pv[i].x*vv[0].w + pv[i].y*vv[1].w + pv[i].z*vv[2].w + pv[i].w*vv[3].w;
            }
        }
    }
#pragma unroll
    for (int i = 0; i < 4; i++) {
        const float inv = 1.0f / l_[i];
        *(float4*)&O[(size_t)(b*SS + q0 + 4*ty + i) * DD + h*64 + 4*tx] =
            make_float4(o_[i][0]*inv, o_[i][1]*inv, o_[i][2]*inv, o_[i][3]*inv);
    }
}

// ---- LayerNorm ----
__device__ __forceinline__ float block_sum_256(float v) {
    __shared__ float red[8];
    const int lane = threadIdx.x & 31, w = threadIdx.x >> 5;
#pragma unroll
    for (int off = 16; off; off >>= 1) v += __shfl_xor_sync(0xffffffffu, v, off);
    __syncthreads();
    if (lane == 0) red[w] = v;
    __syncthreads();
    return red[0]+red[1]+red[2]+red[3]+red[4]+red[5]+red[6]+red[7];
}
__global__ __launch_bounds__(256)
void ln_kernel(const float* __restrict__ Y, const float* __restrict__ R,
               const float* __restrict__ g, const float* __restrict__ bta,
               float* __restrict__ out) {
    const int row = blockIdx.x, tid = threadIdx.x;
    float4 v = ((const float4*)(Y + (size_t)row * DD))[tid];
    const float4 r = ((const float4*)(R + (size_t)row * DD))[tid];
    v.x += r.x; v.y += r.y; v.z += r.z; v.w += r.w;
    const float mean = block_sum_256(v.x + v.y + v.z + v.w) * (1.0f/1024.0f);
    const float dx = v.x-mean, dy = v.y-mean, dz = v.z-mean, dw = v.w-mean;
    const float rstd = rsqrtf(block_sum_256(dx*dx + dy*dy + dz*dz + dw*dw) * (1.0f/1024.0f) + 1e-12f);
    const float4 gg = ((const float4*)g)[tid];
    const float4 bb = ((const float4*)bta)[tid];
    float4 o;
    o.x = dx*rstd*gg.x + bb.x; o.y = dy*rstd*gg.y + bb.y;
    o.z = dz*rstd*gg.z + bb.z; o.w = dw*rstd*gg.w + bb.w;
    ((float4*)(out + (size_t)row * DD))[tid] = o;
}

extern "C" void kernel_launch(void* const* d_in, const int* in_sizes, int n_in,
                              void* d_out, int out_size) {
    const float* x    = (const float*)d_in[0];
    const float* mask = (const float*)d_in[1];
    const float* Wq = (const float*)d_in[2];  const float* bq = (const float*)d_in[3];
    const float* Wk = (const float*)d_in[4];  const float* bk = (const float*)d_in[5];
    const float* Wv = (const float*)d_in[6];  const float* bv = (const float*)d_in[7];
    const float* Wo = (const float*)d_in[8];  const float* bo = (const float*)d_in[9];
    const float* ln1g = (const float*)d_in[10]; const float* ln1b = (const float*)d_in[11];
    const float* Wi = (const float*)d_in[12]; const float* bi = (const float*)d_in[13];
    const float* Wo2 = (const float*)d_in[14]; const float* bo2 = (const float*)d_in[15];
    const float* ln2g = (const float*)d_in[16]; const float* ln2b = (const float*)d_in[17];
    float* out = (float*)d_out;

    float *qkv, *ctx, *tmp, *attn, *b3;
    __nv_bfloat16 *ah, *al, *fh, *fl, *wh, *wl;
    cudaGetSymbolAddress((void**)&qkv, g_qkv);
    cudaGetSymbolAddress((void**)&ctx, g_ctx);
    cudaGetSymbolAddress((void**)&tmp, g_tmp);
    cudaGetSymbolAddress((void**)&attn, g_attn);
    cudaGetSymbolAddress((void**)&b3, g_b3);
    cudaGetSymbolAddress((void**)&ah, g_ah);
    cudaGetSymbolAddress((void**)&al, g_al);
    cudaGetSymbolAddress((void**)&fh, g_fh);
    cudaGetSymbolAddress((void**)&fl, g_fl);
    cudaGetSymbolAddress((void**)&wh, g_wh);
    cudaGetSymbolAddress((void**)&wl, g_wl);

    cudaFuncSetAttribute(gemm_tc, cudaFuncAttributeMaxDynamicSharedMemorySize, GSMEM);

    const dim3 tblk(32, 8);
    wsplit_kernel<<<dim3(32, 32),  tblk>>>(Wq,  DD,   DD,   wh + W_QKV,            wl + W_QKV);
    wsplit_kernel<<<dim3(32, 32),  tblk>>>(Wk,  DD,   DD,   wh + W_QKV + 1048576u, wl + W_QKV + 1048576u);
    wsplit_kernel<<<dim3(32, 32),  tblk>>>(Wv,  DD,   DD,   wh + W_QKV + 2097152u, wl + W_QKV + 2097152u);
    wsplit_kernel<<<dim3(32, 32),  tblk>>>(Wo,  DD,   DD,   wh + W_O,  wl + W_O);
    wsplit_kernel<<<dim3(128, 32), tblk>>>(Wi,  DFFN, DD,   wh + W_I,  wl + W_I);
    wsplit_kernel<<<dim3(32, 128), tblk>>>(Wo2, DD,   DFFN, wh + W_O2, wl + W_O2);
    pack3_kernel<<<3, 1024>>>(bq, bk, bv, b3);

    split_kernel<<<2048, 256>>>(x, ah, al, MM * DD / 4);
    gemm_tc<<<dim3(QKVW/128, MM/128), 256, GSMEM>>>(ah, al, wh + W_QKV, wl + W_QKV, b3,
                                                    qkv, 0, 0, QKVW, DD, 0);
    attn_kernel<<<dim3(SS/64, BB*16), 256>>>(qkv, mask, ctx);

    split_kernel<<<2048, 256>>>(ctx, ah, al, MM * DD / 4);
    gemm_tc<<<dim3(DD/128, MM/128), 256, GSMEM>>>(ah, al, wh + W_O, wl + W_O, bo,
                                                  tmp, 0, 0, DD, DD, 0);
    ln_kernel<<<MM, 256>>>(tmp, x, ln1g, ln1b, attn);

    split_kernel<<<2048, 256>>>(attn, ah, al, MM * DD / 4);
    gemm_tc<<<dim3(DFFN/128, MM/128), 256, GSMEM>>>(ah, al, wh + W_I, wl + W_I, bi,
                                                    0, fh, fl, DFFN, DD, 1);
    gemm_tc<<<dim3(DD/128, MM/128), 256, GSMEM>>>(fh, fl, wh + W_O2, wl + W_O2, bo2,
                                                  tmp, 0, 0, DD, DFFN, 0);
    ln_kernel<<<MM, 256>>>(tmp, attn, ln2g, ln2b, out);
}

// round 6
// speedup vs baseline: 3.3007x; 1.6357x over previous
#include <cuda_runtime.h>
#include <cuda_bf16.h>
#include <cuda_fp16.h>
#include <math.h>
#include <stdint.h>

#define BB 4
#define SS 2048
#define DD 1024
#define DFFN 4096
#define MM (BB*SS)
#define QKVW 3072
#define L2E 1.44269504088896f

__device__ float g_tmp[(size_t)MM * DD];
__device__ float g_res[(size_t)MM * DD];
__device__ __nv_bfloat16 g_ah[(size_t)MM * DD], g_al[(size_t)MM * DD];
__device__ __nv_bfloat16 g_qh[(size_t)MM * DD], g_ql[(size_t)MM * DD];
__device__ __nv_bfloat16 g_kh[(size_t)MM * DD], g_kl[(size_t)MM * DD];
__device__ __half        g_vh[(size_t)MM * DD], g_vl[(size_t)MM * DD];
__device__ __nv_bfloat16 g_ch[(size_t)MM * DD], g_cl[(size_t)MM * DD];
__device__ __nv_bfloat16 g_fh[(size_t)MM * DFFN], g_fl[(size_t)MM * DFFN];
#define W_QKV 0u
#define W_O   (3u*1024*1024)
#define W_I   (4u*1024*1024)
#define W_O2  (8u*1024*1024)
__device__ __nv_bfloat16 g_wh[12u*1024*1024], g_wl[12u*1024*1024];
__device__ float g_b3[QKVW];

__device__ __forceinline__ float gelu_f(float x) {
    return 0.5f * x * (1.0f + erff(x * 0.70710678118654752f));
}
__device__ __forceinline__ uint32_t s2u(const void* p) {
    uint32_t a;
    asm("{ .reg .u64 t; cvta.to.shared.u64 t, %1; cvt.u32.u64 %0, t; }" : "=r"(a) : "l"(p));
    return a;
}
__device__ __forceinline__ uint32_t swz(uint32_t off) {
    return off ^ (((off >> 7) & 7u) << 4);
}
__device__ __forceinline__ void cpa(uint32_t dst, const void* src) {
    asm volatile("cp.async.cg.shared.global [%0], [%1], 16;" :: "r"(dst), "l"(src));
}
__device__ __forceinline__ void ldsm4(uint32_t* r, uint32_t addr) {
    asm volatile("ldmatrix.sync.aligned.m8n8.x4.shared.b16 {%0,%1,%2,%3}, [%4];"
        : "=r"(r[0]), "=r"(r[1]), "=r"(r[2]), "=r"(r[3]) : "r"(addr));
}
__device__ __forceinline__ void ldsm4t(uint32_t* r, uint32_t addr) {
    asm volatile("ldmatrix.sync.aligned.m8n8.x4.trans.shared.b16 {%0,%1,%2,%3}, [%4];"
        : "=r"(r[0]), "=r"(r[1]), "=r"(r[2]), "=r"(r[3]) : "r"(addr));
}
__device__ __forceinline__ void mma16816(float* d, const uint32_t* a, const uint32_t* b) {
    asm volatile("mma.sync.aligned.m16n8k16.row.col.f32.bf16.bf16.f32 "
        "{%0,%1,%2,%3}, {%4,%5,%6,%7}, {%8,%9}, {%0,%1,%2,%3};"
        : "+f"(d[0]), "+f"(d[1]), "+f"(d[2]), "+f"(d[3])
        : "r"(a[0]), "r"(a[1]), "r"(a[2]), "r"(a[3]), "r"(b[0]), "r"(b[1]));
}
__device__ __forceinline__ void mmaf16(float* d, const uint32_t* a, const uint32_t* b) {
    asm volatile("mma.sync.aligned.m16n8k16.row.col.f32.f16.f16.f32 "
        "{%0,%1,%2,%3}, {%4,%5,%6,%7}, {%8,%9}, {%0,%1,%2,%3};"
        : "+f"(d[0]), "+f"(d[1]), "+f"(d[2]), "+f"(d[3])
        : "r"(a[0]), "r"(a[1]), "r"(a[2]), "r"(a[3]), "r"(b[0]), "r"(b[1]));
}
// pack (even->lo, odd->hi) then 2^x on both halves
__device__ __forceinline__ uint32_t exp2_pack(float odd, float even) {
    uint32_t p, r;
    asm("cvt.rn.f16x2.f32 %0, %1, %2;" : "=r"(p) : "f"(odd), "f"(even));
    asm("ex2.approx.f16x2 %0, %1;" : "=r"(r) : "r"(p));
    return r;
}

// W [K,N] fp32 -> hi/lo [N,K] bf16
__global__ __launch_bounds__(256)
void wsplit_kernel(const float* __restrict__ W, int N, int K,
                   __nv_bfloat16* __restrict__ hi, __nv_bfloat16* __restrict__ lo) {
    __shared__ float t[32][33];
    const int tx = threadIdx.x, ty = threadIdx.y;
    const int n0 = blockIdx.x * 32, k0 = blockIdx.y * 32;
    for (int j = ty; j < 32; j += 8) t[j][tx] = W[(size_t)(k0 + j) * N + n0 + tx];
    __syncthreads();
    for (int j = ty; j < 32; j += 8) {
        const float w = t[tx][j];
        const size_t o = (size_t)(n0 + j) * K + k0 + tx;
        const __nv_bfloat16 h = __float2bfloat16_rn(w);
        hi[o] = h;
        lo[o] = __float2bfloat16_rn(w - __bfloat162float(h));
    }
}

__global__ __launch_bounds__(256)
void split_kernel(const float* __restrict__ in, __nv_bfloat16* __restrict__ hi,
                  __nv_bfloat16* __restrict__ lo, int n4) {
    for (int i = blockIdx.x * 256 + threadIdx.x; i < n4; i += gridDim.x * 256) {
        const float4 v = ((const float4*)in)[i];
        const __nv_bfloat16 h0 = __float2bfloat16_rn(v.x), h1 = __float2bfloat16_rn(v.y);
        const __nv_bfloat16 h2 = __float2bfloat16_rn(v.z), h3 = __float2bfloat16_rn(v.w);
        ((__nv_bfloat162*)hi)[2*i+0] = __halves2bfloat162(h0, h1);
        ((__nv_bfloat162*)hi)[2*i+1] = __halves2bfloat162(h2, h3);
        ((__nv_bfloat162*)lo)[2*i+0] = __halves2bfloat162(
            __float2bfloat16_rn(v.x - __bfloat162float(h0)),
            __float2bfloat16_rn(v.y - __bfloat162float(h1)));
        ((__nv_bfloat162*)lo)[2*i+1] = __halves2bfloat162(
            __float2bfloat16_rn(v.z - __bfloat162float(h2)),
            __float2bfloat16_rn(v.w - __bfloat162float(h3)));
    }
}

__global__ void pack3_kernel(const float* a, const float* b, const float* c, float* o) {
    const float* s = (blockIdx.x == 0) ? a : (blockIdx.x == 1) ? b : c;
    o[blockIdx.x * 1024 + threadIdx.x] = s[threadIdx.x];
}

// ---- mma.sync bf16 GEMM, CTA 128x128, BK=64, 3-stage cp.async, 3-term split --
#define STG_B 65536
#define T_AH 0
#define T_AL 16384
#define T_BH 32768
#define T_BL 49152
#define GSMEM (3*STG_B)

__device__ __forceinline__ void load_stage(uint32_t sbase,
    const __nv_bfloat16* __restrict__ Ah, const __nv_bfloat16* __restrict__ Al,
    const __nv_bfloat16* __restrict__ Bh, const __nv_bfloat16* __restrict__ Bl,
    int K, int m0, int n0, int kb) {
    for (int i = threadIdx.x; i < 1024; i += 256) {
        const int row = i >> 3, cc = (i & 7) << 3;
        const uint32_t so = swz((uint32_t)(row * 128 + cc * 2));
        const size_t ka = (size_t)(m0 + row) * K + kb + cc;
        const size_t kbx = (size_t)(n0 + row) * K + kb + cc;
        cpa(sbase + T_AH + so, Ah + ka);
        cpa(sbase + T_AL + so, Al + ka);
        cpa(sbase + T_BH + so, Bh + kbx);
        cpa(sbase + T_BL + so, Bl + kbx);
    }
}

// mode 0: Cf fp32. mode 1: Ch/Cl bf16 split (+act). mode 2: qkv split out.
__global__ __launch_bounds__(256, 1)
void gemm_tc(const __nv_bfloat16* __restrict__ Ah, const __nv_bfloat16* __restrict__ Al,
             const __nv_bfloat16* __restrict__ Bh, const __nv_bfloat16* __restrict__ Bl,
             const float* __restrict__ bias, float* __restrict__ Cf,
             __nv_bfloat16* __restrict__ Ch, __nv_bfloat16* __restrict__ Cl,
             __nv_bfloat16* __restrict__ KH2, __nv_bfloat16* __restrict__ KL2,
             __half* __restrict__ VH2, __half* __restrict__ VL2,
             int N, int K, int act, int mode) {
    extern __shared__ char smv[];
    const uint32_t sb = s2u(smv);
    const int tid = threadIdx.x, lane = tid & 31, wid = tid >> 5;
    const int wm = wid & 3, wn = wid >> 2;
    const int m0 = blockIdx.y << 7, n0 = blockIdx.x << 7;
    const int nc = K >> 6;

    float acc[2][8][4];
#pragma unroll
    for (int i = 0; i < 2; i++)
#pragma unroll
        for (int j = 0; j < 8; j++)
#pragma unroll
            for (int q = 0; q < 4; q++) acc[i][j][q] = 0.0f;

    load_stage(sb, Ah, Al, Bh, Bl, K, m0, n0, 0);
    asm volatile("cp.async.commit_group;" ::: "memory");
    load_stage(sb + STG_B, Ah, Al, Bh, Bl, K, m0, n0, 64);
    asm volatile("cp.async.commit_group;" ::: "memory");

    const int a_r = (lane & 15);
    const int a_c = (lane >> 4) << 3;
    const int b_r = (lane & 7) + ((lane >> 4) << 3);
    const int b_c = ((lane >> 3) & 1) << 3;

    for (int c = 0; c < nc; c++) {
        if (c + 2 < nc)
            load_stage(sb + (uint32_t)((c + 2) % 3) * STG_B, Ah, Al, Bh, Bl,
                       K, m0, n0, (c + 2) << 6);
        asm volatile("cp.async.commit_group;" ::: "memory");
        asm volatile("cp.async.wait_group 2;" ::: "memory");
        __syncthreads();

        const uint32_t st = sb + (uint32_t)(c % 3) * STG_B;
#pragma unroll
        for (int ks = 0; ks < 4; ks++) {
            uint32_t afh[2][4], afl[2][4], bfh[8][2], bfl[8][2];
#pragma unroll
            for (int mt = 0; mt < 2; mt++) {
                const uint32_t off = swz((uint32_t)((wm*32 + mt*16 + a_r)*128 + (ks*16 + a_c)*2));
                ldsm4(afh[mt], st + T_AH + off);
                ldsm4(afl[mt], st + T_AL + off);
            }
#pragma unroll
            for (int p = 0; p < 4; p++) {
                const uint32_t off = swz((uint32_t)((wn*64 + p*16 + b_r)*128 + (ks*16 + b_c)*2));
                uint32_t t4[4];
                ldsm4(t4, st + T_BH + off);
                bfh[2*p][0]=t4[0]; bfh[2*p][1]=t4[1]; bfh[2*p+1][0]=t4[2]; bfh[2*p+1][1]=t4[3];
                ldsm4(t4, st + T_BL + off);
                bfl[2*p][0]=t4[0]; bfl[2*p][1]=t4[1]; bfl[2*p+1][0]=t4[2]; bfl[2*p+1][1]=t4[3];
            }
#pragma unroll
            for (int mt = 0; mt < 2; mt++)
#pragma unroll
                for (int nt = 0; nt < 8; nt++) {
                    mma16816(acc[mt][nt], afh[mt], bfh[nt]);
                    mma16816(acc[mt][nt], afh[mt], bfl[nt]);
                    mma16816(acc[mt][nt], afl[mt], bfh[nt]);
                }
        }
        __syncthreads();
    }

    const int rbase = m0 + wm * 32 + (lane >> 2);
    const int cbase = n0 + wn * 64 + ((lane & 3) << 1);
    const int region = n0 >> 10;
#pragma unroll
    for (int mt = 0; mt < 2; mt++) {
#pragma unroll
        for (int nt = 0; nt < 8; nt++) {
            const int col = cbase + nt * 8;
            const float2 bv = *(const float2*)&bias[col];
            float v0 = acc[mt][nt][0] + bv.x, v1 = acc[mt][nt][1] + bv.y;
            float v2 = acc[mt][nt][2] + bv.x, v3 = acc[mt][nt][3] + bv.y;
            if (act) { v0 = gelu_f(v0); v1 = gelu_f(v1); v2 = gelu_f(v2); v3 = gelu_f(v3); }
            const size_t r0 = (size_t)(rbase + mt * 16);
            const size_t r1 = r0 + 8;
            if (mode == 0) {
                *(float2*)&Cf[r0 * N + col] = make_float2(v0, v1);
                *(float2*)&Cf[r1 * N + col] = make_float2(v2, v3);
            } else if (mode == 1) {
                const __nv_bfloat16 h0 = __float2bfloat16_rn(v0), h1 = __float2bfloat16_rn(v1);
                const __nv_bfloat16 h2 = __float2bfloat16_rn(v2), h3 = __float2bfloat16_rn(v3);
                *(__nv_bfloat162*)&Ch[r0 * N + col] = __halves2bfloat162(h0, h1);
                *(__nv_bfloat162*)&Ch[r1 * N + col] = __halves2bfloat162(h2, h3);
                *(__nv_bfloat162*)&Cl[r0 * N + col] = __halves2bfloat162(
                    __float2bfloat16_rn(v0 - __bfloat162float(h0)),
                    __float2bfloat16_rn(v1 - __bfloat162float(h1)));
                *(__nv_bfloat162*)&Cl[r1 * N + col] = __halves2bfloat162(
                    __float2bfloat16_rn(v2 - __bfloat162float(h2)),
                    __float2bfloat16_rn(v3 - __bfloat162float(h3)));
            } else {
                const size_t cl_ = (size_t)(col - (region << 10));
                if (region < 2) {
                    __nv_bfloat16* H = region ? KH2 : Ch;
                    __nv_bfloat16* L = region ? KL2 : Cl;
                    const __nv_bfloat16 h0 = __float2bfloat16_rn(v0), h1 = __float2bfloat16_rn(v1);
                    const __nv_bfloat16 h2 = __float2bfloat16_rn(v2), h3 = __float2bfloat16_rn(v3);
                    *(__nv_bfloat162*)&H[r0 * DD + cl_] = __halves2bfloat162(h0, h1);
                    *(__nv_bfloat162*)&H[r1 * DD + cl_] = __halves2bfloat162(h2, h3);
                    *(__nv_bfloat162*)&L[r0 * DD + cl_] = __halves2bfloat162(
                        __float2bfloat16_rn(v0 - __bfloat162float(h0)),
                        __float2bfloat16_rn(v1 - __bfloat162float(h1)));
                    *(__nv_bfloat162*)&L[r1 * DD + cl_] = __halves2bfloat162(
                        __float2bfloat16_rn(v2 - __bfloat162float(h2)),
                        __float2bfloat16_rn(v3 - __bfloat162float(h3)));
                } else {
                    const __half h0 = __float2half_rn(v0), h1 = __float2half_rn(v1);
                    const __half h2 = __float2half_rn(v2), h3 = __float2half_rn(v3);
                    *(__half2*)&VH2[r0 * DD + cl_] = __halves2half2(h0, h1);
                    *(__half2*)&VH2[r1 * DD + cl_] = __halves2half2(h2, h3);
                    *(__half2*)&VL2[r0 * DD + cl_] = __halves2half2(
                        __float2half_rn(v0 - __half2float(h0)),
                        __float2half_rn(v1 - __half2float(h1)));
                    *(__half2*)&VL2[r1 * DD + cl_] = __halves2half2(
                        __float2half_rn(v2 - __half2float(h2)),
                        __float2half_rn(v3 - __half2float(h3)));
                }
            }
        }
    }
}

// ---- tensor-core flash attention: 128 q-rows/CTA, f16x2 exp, split QK/V ----
#define AT_QH 0
#define AT_QL 16384
#define AT_ST 32768
#define AT_SSZ 33024
#define AT_SMEM (32768 + 3*33024)

__global__ __launch_bounds__(256, 1)
void attn_mma(const __nv_bfloat16* __restrict__ qh, const __nv_bfloat16* __restrict__ ql,
              const __nv_bfloat16* __restrict__ kh, const __nv_bfloat16* __restrict__ kl,
              const __half* __restrict__ vh, const __half* __restrict__ vl,
              const float* __restrict__ mask,
              __nv_bfloat16* __restrict__ ch, __nv_bfloat16* __restrict__ cl) {
    extern __shared__ char smv[];
    const uint32_t sb = s2u(smv);
    const int tid = threadIdx.x, lane = tid & 31, wid = tid >> 5;
    const int b = blockIdx.y >> 4, h = blockIdx.y & 15;
    const int q0 = blockIdx.x << 7;
    const size_t hoff = (size_t)h * 64;

    // Q hi/lo tiles: 128 rows x 64 cols bf16
    for (int i = tid; i < 2048; i += 256) {
        const int t = i >> 10, idx = i & 1023, row = idx >> 3, cc = idx & 7;
        const __nv_bfloat16* src = (t ? ql : qh) + (size_t)(b*SS + q0 + row)*DD + hoff + cc*8;
        cpa(sb + AT_QH + t*16384 + swz((uint32_t)(row*128 + cc*16)), src);
    }
    // stages 0,1
    for (int sidx = 0; sidx < 2; sidx++) {
        const int kt = sidx << 6;
        const uint32_t base = sb + AT_ST + (uint32_t)sidx * AT_SSZ;
        for (int i = tid; i < 2048; i += 256) {
            const int t = i >> 9, idx = i & 511, row = idx >> 3, cc = idx & 7;
            const uint32_t dst = base + t*8192 + swz((uint32_t)(row*128 + cc*16));
            const size_t goff = (size_t)(b*SS + kt + row)*DD + hoff + cc*8;
            if (t == 0) cpa(dst, kh + goff);
            else if (t == 1) cpa(dst, kl + goff);
            else if (t == 2) cpa(dst, vh + goff);
            else cpa(dst, vl + goff);
        }
        if (tid < 16) cpa(base + 32768 + tid*16, mask + (size_t)b*SS + kt + tid*4);
        asm volatile("cp.async.commit_group;" ::: "memory");
    }

    uint32_t qfh[4][4], qfl[4][4];
    float o[8][4], lacc[4];
    float mL0 = -1e30f, mL1 = -1e30f;
#pragma unroll
    for (int nt = 0; nt < 8; nt++) { o[nt][0]=o[nt][1]=o[nt][2]=o[nt][3]=0.f; }
    lacc[0]=lacc[1]=lacc[2]=lacc[3]=0.f;
    const uint32_t ones2[2] = {0x3C003C00u, 0x3C003C00u};

    for (int c = 0; c < SS/64; c++) {
        if (c + 2 < SS/64) {
            const int kt = (c + 2) << 6;
            const uint32_t base = sb + AT_ST + (uint32_t)((c+2) % 3) * AT_SSZ;
            for (int i = tid; i < 2048; i += 256) {
                const int t = i >> 9, idx = i & 511, row = idx >> 3, cc = idx & 7;
                const uint32_t dst = base + t*8192 + swz((uint32_t)(row*128 + cc*16));
                const size_t goff = (size_t)(b*SS + kt + row)*DD + hoff + cc*8;
                if (t == 0) cpa(dst, kh + goff);
                else if (t == 1) cpa(dst, kl + goff);
                else if (t == 2) cpa(dst, vh + goff);
                else cpa(dst, vl + goff);
            }
            if (tid < 16) cpa(base + 32768 + tid*16, mask + (size_t)b*SS + kt + tid*4);
        }
        asm volatile("cp.async.commit_group;" ::: "memory");
        asm volatile("cp.async.wait_group 2;" ::: "memory");
        __syncthreads();

        if (c == 0) {
#pragma unroll
            for (int ks = 0; ks < 4; ks++) {
                const int row = wid*16 + (lane & 15);
                const int colb = (ks*16 + ((lane >> 4) << 3)) * 2;
                ldsm4(qfh[ks], sb + AT_QH + swz((uint32_t)(row*128 + colb)));
                ldsm4(qfl[ks], sb + AT_QL + swz((uint32_t)(row*128 + colb)));
            }
        }

        const uint32_t soff = AT_ST + (uint32_t)(c % 3) * AT_SSZ;
        const uint32_t st = sb + soff;
        float S[8][4];
#pragma unroll
        for (int nt = 0; nt < 8; nt++) { S[nt][0]=S[nt][1]=S[nt][2]=S[nt][3]=0.f; }
#pragma unroll
        for (int ks = 0; ks < 4; ks++) {
            uint32_t kbh[8][2], kbl[8][2];
#pragma unroll
            for (int p = 0; p < 4; p++) {
                const int row = p*16 + (lane & 7) + ((lane >> 4) << 3);
                const int colb = (ks*16 + (((lane >> 3) & 1) << 3)) * 2;
                uint32_t t4[4];
                ldsm4(t4, st + swz((uint32_t)(row*128 + colb)));
                kbh[2*p][0]=t4[0]; kbh[2*p][1]=t4[1]; kbh[2*p+1][0]=t4[2]; kbh[2*p+1][1]=t4[3];
                ldsm4(t4, st + 8192 + swz((uint32_t)(row*128 + colb)));
                kbl[2*p][0]=t4[0]; kbl[2*p][1]=t4[1]; kbl[2*p+1][0]=t4[2]; kbl[2*p+1][1]=t4[3];
            }
#pragma unroll
            for (int nt = 0; nt < 8; nt++) {
                mma16816(S[nt], qfh[ks], kbh[nt]);
                mma16816(S[nt], qfh[ks], kbl[nt]);
                mma16816(S[nt], qfl[ks], kbh[nt]);
            }
        }
        // scale + mask
#pragma unroll
        for (int nt = 0; nt < 8; nt++) {
            const float2 mv = *(const float2*)(smv + soff + 32768 + (8*nt + 2*(lane&3))*4);
            S[nt][0] = fmaf(S[nt][0], 0.125f, mv.x);
            S[nt][1] = fmaf(S[nt][1], 0.125f, mv.y);
            S[nt][2] = fmaf(S[nt][2], 0.125f, mv.x);
            S[nt][3] = fmaf(S[nt][3], 0.125f, mv.y);
        }
        float mx0 = -1e30f, mx1 = -1e30f;
#pragma unroll
        for (int nt = 0; nt < 8; nt++) {
            mx0 = fmaxf(mx0, fmaxf(S[nt][0], S[nt][1]));
            mx1 = fmaxf(mx1, fmaxf(S[nt][2], S[nt][3]));
        }
        mx0 = fmaxf(mx0, __shfl_xor_sync(~0u, mx0, 1));
        mx0 = fmaxf(mx0, __shfl_xor_sync(~0u, mx0, 2));
        mx1 = fmaxf(mx1, __shfl_xor_sync(~0u, mx1, 1));
        mx1 = fmaxf(mx1, __shfl_xor_sync(~0u, mx1, 2));
        const float mLn0 = fmaxf(mL0, mx0 * L2E);
        const float mLn1 = fmaxf(mL1, mx1 * L2E);
        const float corr0 = exp2f(mL0 - mLn0);
        const float corr1 = exp2f(mL1 - mLn1);
        mL0 = mLn0; mL1 = mLn1;
        lacc[0] *= corr0; lacc[1] *= corr0; lacc[2] *= corr1; lacc[3] *= corr1;
#pragma unroll
        for (int nt = 0; nt < 8; nt++) {
            o[nt][0] *= corr0; o[nt][1] *= corr0; o[nt][2] *= corr1; o[nt][3] *= corr1;
        }
        uint32_t pf[4][4];
#pragma unroll
        for (int j = 0; j < 4; j++) {
            pf[j][0] = exp2_pack(fmaf(S[2*j][1],   L2E, -mL0), fmaf(S[2*j][0],   L2E, -mL0));
            pf[j][1] = exp2_pack(fmaf(S[2*j][3],   L2E, -mL1), fmaf(S[2*j][2],   L2E, -mL1));
            pf[j][2] = exp2_pack(fmaf(S[2*j+1][1], L2E, -mL0), fmaf(S[2*j+1][0], L2E, -mL0));
            pf[j][3] = exp2_pack(fmaf(S[2*j+1][3], L2E, -mL1), fmaf(S[2*j+1][2], L2E, -mL1));
        }
#pragma unroll
        for (int j = 0; j < 4; j++) mmaf16(lacc, pf[j], ones2);
#pragma unroll
        for (int j = 0; j < 4; j++) {
            const int krow = j*16 + (lane & 15);
#pragma unroll
            for (int pp = 0; pp < 4; pp++) {
                const int colb = (pp*16 + ((lane >> 4) << 3)) * 2;
                uint32_t vf[4];
                ldsm4t(vf, st + 16384 + swz((uint32_t)(krow*128 + colb)));
                mmaf16(o[2*pp],   pf[j], vf);
                mmaf16(o[2*pp+1], pf[j], vf + 2);
                ldsm4t(vf, st + 24576 + swz((uint32_t)(krow*128 + colb)));
                mmaf16(o[2*pp],   pf[j], vf);
                mmaf16(o[2*pp+1], pf[j], vf + 2);
            }
        }
        __syncthreads();
    }

    const float inv0 = 1.0f / lacc[0];
    const float inv1 = 1.0f / lacc[2];
    const size_t r0 = (size_t)(b*SS + q0 + wid*16 + (lane >> 2));
    const size_t r1 = r0 + 8;
#pragma unroll
    for (int nt = 0; nt < 8; nt++) {
        const size_t col = hoff + 8*nt + 2*(lane & 3);
        const float v0 = o[nt][0]*inv0, v1 = o[nt][1]*inv0;
        const float v2 = o[nt][2]*inv1, v3 = o[nt][3]*inv1;
        const __nv_bfloat16 h0 = __float2bfloat16_rn(v0), h1 = __float2bfloat16_rn(v1);
        const __nv_bfloat16 h2 = __float2bfloat16_rn(v2), h3 = __float2bfloat16_rn(v3);
        *(__nv_bfloat162*)&ch[r0*DD + col] = __halves2bfloat162(h0, h1);
        *(__nv_bfloat162*)&ch[r1*DD + col] = __halves2bfloat162(h2, h3);
        *(__nv_bfloat162*)&cl[r0*DD + col] = __halves2bfloat162(
            __float2bfloat16_rn(v0 - __bfloat162float(h0)),
            __float2bfloat16_rn(v1 - __bfloat162float(h1)));
        *(__nv_bfloat162*)&cl[r1*DD + col] = __halves2bfloat162(
            __float2bfloat16_rn(v2 - __bfloat162float(h2)),
            __float2bfloat16_rn(v3 - __bfloat162float(h3)));
    }
}

// ---- LayerNorm (optionally emits bf16 hi/lo of its output) ----
__device__ __forceinline__ float block_sum_256(float v) {
    __shared__ float red[8];
    const int lane = threadIdx.x & 31, w = threadIdx.x >> 5;
#pragma unroll
    for (int off = 16; off; off >>= 1) v += __shfl_xor_sync(0xffffffffu, v, off);
    __syncthreads();
    if (lane == 0) red[w] = v;
    __syncthreads();
    return red[0]+red[1]+red[2]+red[3]+red[4]+red[5]+red[6]+red[7];
}
__global__ __launch_bounds__(256)
void ln_kernel(const float* __restrict__ Y, const float* __restrict__ R,
               const float* __restrict__ g, const float* __restrict__ bta,
               float* __restrict__ out,
               __nv_bfloat16* __restrict__ hi, __nv_bfloat16* __restrict__ lo) {
    const int row = blockIdx.x, tid = threadIdx.x;
    float4 v = ((const float4*)(Y + (size_t)row * DD))[tid];
    const float4 r = ((const float4*)(R + (size_t)row * DD))[tid];
    v.x += r.x; v.y += r.y; v.z += r.z; v.w += r.w;
    const float mean = block_sum_256(v.x + v.y + v.z + v.w) * (1.0f/1024.0f);
    const float dx = v.x-mean, dy = v.y-mean, dz = v.z-mean, dw = v.w-mean;
    const float rstd = rsqrtf(block_sum_256(dx*dx + dy*dy + dz*dz + dw*dw) * (1.0f/1024.0f) + 1e-12f);
    const float4 gg = ((const float4*)g)[tid];
    const float4 bb = ((const float4*)bta)[tid];
    float4 o;
    o.x = dx*rstd*gg.x + bb.x; o.y = dy*rstd*gg.y + bb.y;
    o.z = dz*rstd*gg.z + bb.z; o.w = dw*rstd*gg.w + bb.w;
    ((float4*)(out + (size_t)row * DD))[tid] = o;
    if (hi) {
        const __nv_bfloat16 h0 = __float2bfloat16_rn(o.x), h1 = __float2bfloat16_rn(o.y);
        const __nv_bfloat16 h2 = __float2bfloat16_rn(o.z), h3 = __float2bfloat16_rn(o.w);
        ((__nv_bfloat162*)(hi + (size_t)row * DD))[2*tid]   = __halves2bfloat162(h0, h1);
        ((__nv_bfloat162*)(hi + (size_t)row * DD))[2*tid+1] = __halves2bfloat162(h2, h3);
        ((__nv_bfloat162*)(lo + (size_t)row * DD))[2*tid] = __halves2bfloat162(
            __float2bfloat16_rn(o.x - __bfloat162float(h0)),
            __float2bfloat16_rn(o.y - __bfloat162float(h1)));
        ((__nv_bfloat162*)(lo + (size_t)row * DD))[2*tid+1] = __halves2bfloat162(
            __float2bfloat16_rn(o.z - __bfloat162float(h2)),
            __float2bfloat16_rn(o.w - __bfloat162float(h3)));
    }
}

extern "C" void kernel_launch(void* const* d_in, const int* in_sizes, int n_in,
                              void* d_out, int out_size) {
    const float* x    = (const float*)d_in[0];
    const float* mask = (const float*)d_in[1];
    const float* Wq = (const float*)d_in[2];  const float* bq = (const float*)d_in[3];
    const float* Wk = (const float*)d_in[4];  const float* bk = (const float*)d_in[5];
    const float* Wv = (const float*)d_in[6];  const float* bv = (const float*)d_in[7];
    const float* Wo = (const float*)d_in[8];  const float* bo = (const float*)d_in[9];
    const float* ln1g = (const float*)d_in[10]; const float* ln1b = (const float*)d_in[11];
    const float* Wi = (const float*)d_in[12]; const float* bi = (const float*)d_in[13];
    const float* Wo2 = (const float*)d_in[14]; const float* bo2 = (const float*)d_in[15];
    const float* ln2g = (const float*)d_in[16]; const float* ln2b = (const float*)d_in[17];
    float* out = (float*)d_out;

    float *tmp, *res, *b3;
    __nv_bfloat16 *ah, *al, *qhp, *qlp, *khp, *klp, *chp, *clp, *fh, *fl, *wh, *wl;
    __half *vhp, *vlp;
    cudaGetSymbolAddress((void**)&tmp, g_tmp);
    cudaGetSymbolAddress((void**)&res, g_res);
    cudaGetSymbolAddress((void**)&b3, g_b3);
    cudaGetSymbolAddress((void**)&ah, g_ah);
    cudaGetSymbolAddress((void**)&al, g_al);
    cudaGetSymbolAddress((void**)&qhp, g_qh);
    cudaGetSymbolAddress((void**)&qlp, g_ql);
    cudaGetSymbolAddress((void**)&khp, g_kh);
    cudaGetSymbolAddress((void**)&klp, g_kl);
    cudaGetSymbolAddress((void**)&vhp, g_vh);
    cudaGetSymbolAddress((void**)&vlp, g_vl);
    cudaGetSymbolAddress((void**)&chp, g_ch);
    cudaGetSymbolAddress((void**)&clp, g_cl);
    cudaGetSymbolAddress((void**)&fh, g_fh);
    cudaGetSymbolAddress((void**)&fl, g_fl);
    cudaGetSymbolAddress((void**)&wh, g_wh);
    cudaGetSymbolAddress((void**)&wl, g_wl);

    cudaFuncSetAttribute(gemm_tc, cudaFuncAttributeMaxDynamicSharedMemorySize, GSMEM);
    cudaFuncSetAttribute(attn_mma, cudaFuncAttributeMaxDynamicSharedMemorySize, AT_SMEM);

    const dim3 tblk(32, 8);
    wsplit_kernel<<<dim3(32, 32),  tblk>>>(Wq,  DD,   DD,   wh + W_QKV,            wl + W_QKV);
    wsplit_kernel<<<dim3(32, 32),  tblk>>>(Wk,  DD,   DD,   wh + W_QKV + 1048576u, wl + W_QKV + 1048576u);
    wsplit_kernel<<<dim3(32, 32),  tblk>>>(Wv,  DD,   DD,   wh + W_QKV + 2097152u, wl + W_QKV + 2097152u);
    wsplit_kernel<<<dim3(32, 32),  tblk>>>(Wo,  DD,   DD,   wh + W_O,  wl + W_O);
    wsplit_kernel<<<dim3(128, 32), tblk>>>(Wi,  DFFN, DD,   wh + W_I,  wl + W_I);
    wsplit_kernel<<<dim3(32, 128), tblk>>>(Wo2, DD,   DFFN, wh + W_O2, wl + W_O2);
    pack3_kernel<<<3, 1024>>>(bq, bk, bv, b3);

    split_kernel<<<2048, 256>>>(x, ah, al, MM * DD / 4);
    gemm_tc<<<dim3(QKVW/128, MM/128), 256, GSMEM>>>(ah, al, wh + W_QKV, wl + W_QKV, b3,
        0, qhp, qlp, khp, klp, vhp, vlp, QKVW, DD, 0, 2);
    attn_mma<<<dim3(SS/128, BB*16), 256, AT_SMEM>>>(qhp, qlp, khp, klp, vhp, vlp, mask, chp, clp);
    gemm_tc<<<dim3(DD/128, MM/128), 256, GSMEM>>>(chp, clp, wh + W_O, wl + W_O, bo,
        tmp, 0, 0, 0, 0, 0, 0, DD, DD, 0, 0);
    ln_kernel<<<MM, 256>>>(tmp, x, ln1g, ln1b, res, ah, al);
    gemm_tc<<<dim3(DFFN/128, MM/128), 256, GSMEM>>>(ah, al, wh + W_I, wl + W_I, bi,
        0, fh, fl, 0, 0, 0, 0, DFFN, DD, 1, 1);
    gemm_tc<<<dim3(DD/128, MM/128), 256, GSMEM>>>(fh, fl, wh + W_O2, wl + W_O2, bo2,
        tmp, 0, 0, 0, 0, 0, 0, DD, DFFN, 0, 0);
    ln_kernel<<<MM, 256>>>(tmp, res, ln2g, ln2b, out, 0, 0);
}